// round 16
// baseline (speedup 1.0000x reference)
#include <cuda_runtime.h>

// ---------------------------------------------------------------------------
// RNN_70480413327462: 59-step patch-grid RNN + 9-neighbor center attention.
// R10: 2D CTA tiles (4x8 patches, 128 CTAs x 32 warps) + LOCAL neighbor sync:
// per-CTA release/acquire flag, each CTA waits only on its 8 tile neighbors.
// Double-buffered smem K/V tiles; halo via __ldcg. No fences, no global bar.
// ---------------------------------------------------------------------------

#define NBLK   128
#define NTHR   1024
#define NWARPS 32
#define PP     4096
#define NROWS  8192
#define HH     32
#define TSTEPS 59
#define NOBS   10
#define KPAD   36
#define TROWS  128                       // rows per tile buffer (64 slots x 2 batch)
#define TBUF   (TROWS * KPAD)            // floats per tile parity
#define INV_SQRT_E 0.1714985851425088f   // 1/sqrt(34)

// double-buffered global K/V (halo exchange only)
__device__ float g_K[2][NROWS * KPAD];
__device__ float g_V[2][NROWS * KPAD];
// per-CTA phase1-complete flags, one 128B line each (monotonic epochs)
__device__ unsigned g_P[NBLK * 32];

__device__ __forceinline__ void stReleaseGpu(unsigned* p, unsigned v) {
    asm volatile("st.release.gpu.u32 [%0], %1;" :: "l"(p), "r"(v) : "memory");
}
__device__ __forceinline__ unsigned ldAcquireGpu(unsigned* p) {
    unsigned v;
    asm volatile("ld.acquire.gpu.u32 %0, [%1];" : "=r"(v) : "l"(p) : "memory");
    return v;
}

struct Smem {
    float4 Wc[32][17];        // c<8: W_x2h chunk c; c>=8: W_h2h chunk c-8
    float4 Wq[32][9];
    float4 Wk[32][9];
    float4 Wv[32][9];
    float4 Mw[32][9];         // (W_fcsa@W_out)^T chunks (9 used)
    float4 Wf[32][9];         // W_fc2 chunks (8 used)
    float4 We[6][9];          // ext rows (q32,q33,k32,k33,v32,v33)
    float4 RB[NWARPS][2][17]; // per-warp stage: [0..8] inp/ht/o, [9..16] h
    float  sQ[2 * TBUF];      // tile q/k/v rows [(slot*2+b)*KPAD], x2 parity
    float  sK[2 * TBUF];
    float  sV[2 * TBUF];
    unsigned base;
};

__device__ __forceinline__ float warpAllSum(float v) {
#pragma unroll
    for (int o = 16; o > 0; o >>= 1) v += __shfl_xor_sync(0xffffffffu, v, o);
    return v;
}

__device__ __forceinline__ float ftanh(float x) {
    float e = __expf(2.f * x);
    return 1.f - __fdividef(2.f, e + 1.f);
}

__device__ __forceinline__ float dot4(float4 a, float4 b) {
    return fmaf(a.x, b.x, fmaf(a.y, b.y, fmaf(a.z, b.z, a.w * b.w)));
}

extern __shared__ unsigned char smem_raw[];

__global__ void __launch_bounds__(NTHR, 1) rnn_kernel(
    const float* __restrict__ x,
    const float* __restrict__ W_x2h, const float* __restrict__ b_x2h,
    const float* __restrict__ W_h2h, const float* __restrict__ b_h2h,
    const float* __restrict__ W_fc2, const float* __restrict__ b_fc2,
    const float* __restrict__ ln_g,  const float* __restrict__ ln_b,
    const float* __restrict__ W_fcsa,const float* __restrict__ b_fcsa,
    const float* __restrict__ W_in,  const float* __restrict__ b_in,
    const float* __restrict__ W_out, const float* __restrict__ b_out,
    float* __restrict__ out)
{
    Smem* sm = reinterpret_cast<Smem*>(smem_raw);
    const int tid = threadIdx.x;
    const int bid = blockIdx.x;

    // ---------------- smem weight init ----------------
    for (int idx = tid; idx < 32 * 16; idx += NTHR) {
        int e = idx >> 4, c = idx & 15;
        const float* src = (c < 8) ? (W_x2h + e * 32 + c * 4)
                                   : (W_h2h + e * 32 + (c - 8) * 4);
        sm->Wc[e][c] = make_float4(src[0], src[1], src[2], src[3]);
    }
    for (int idx = tid; idx < 32 * 8; idx += NTHR) {
        int e = idx >> 3, c = idx & 7, i = c * 4;
        const float* q = W_in + e * 34 + i;
        const float* k = W_in + (34 + e) * 34 + i;
        const float* v = W_in + (68 + e) * 34 + i;
        const float* f = W_fc2 + e * 32 + i;
        sm->Wq[e][c] = make_float4(q[0], q[1], q[2], q[3]);
        sm->Wk[e][c] = make_float4(k[0], k[1], k[2], k[3]);
        sm->Wv[e][c] = make_float4(v[0], v[1], v[2], v[3]);
        sm->Wf[e][c] = make_float4(f[0], f[1], f[2], f[3]);
    }
    for (int idx = tid; idx < 32 * 9; idx += NTHR) {
        int e = idx / 9, c = idx % 9;
        float w[4];
#pragma unroll
        for (int d = 0; d < 4; d++) {
            int f = c * 4 + d;
            float acc = 0.f;
            if (f < 34)
                for (int g = 0; g < 34; g++)
                    acc += W_fcsa[e * 34 + g] * W_out[g * 34 + f];
            w[d] = acc;
        }
        sm->Mw[e][c] = make_float4(w[0], w[1], w[2], w[3]);
    }
    for (int idx = tid; idx < 6 * 8; idx += NTHR) {
        int j = idx >> 3, c = idx & 7;
        int row = (j >> 1) * 34 + 32 + (j & 1);
        const float* src = W_in + row * 34 + c * 4;
        sm->We[j][c] = make_float4(src[0], src[1], src[2], src[3]);
    }
    // zero smem tile pads (elements 34,35 of each row, both parities)
    for (int idx = tid; idx < 2 * TROWS * 2; idx += NTHR) {
        int row = idx >> 1;            // 0..255 (includes parity)
        int off = row * KPAD + 34 + (idx & 1);
        sm->sQ[off] = 0.f; sm->sK[off] = 0.f; sm->sV[off] = 0.f;
    }
    if (tid == 0) sm->base = ldAcquireGpu(&g_P[bid * 32]);  // own flag, stable

    const int lane = tid & 31;
    const int wid  = tid >> 5;

    // 2D tile mapping: 16x8 CTA grid of 4x8 patch tiles
    const int tr = bid >> 3;
    const int tc = bid & 7;
    const int pi = wid >> 3;
    const int pj = wid & 7;
    const int r  = tr * 4 + pi;
    const int cI = tc * 8 + pj;
    const int p  = r * 64 + cI;
    const int ownSlot = wid;

    // neighbor flag pointer for lanes 0..7 of warp 0
    unsigned* nbF = &g_P[bid * 32];
    if (tid < 8) {
        const int dr8[8] = {-1,-1,-1, 0, 0, 1, 1, 1};
        const int dc8[8] = {-1, 0, 1,-1, 1,-1, 0, 1};
        int ntr = tr + dr8[tid], ntc = tc + dc8[tid];
        if (ntr >= 0 && ntr < 16 && ntc >= 0 && ntc < 8)
            nbF = &g_P[(ntr * 8 + ntc) * 32];
    }

    // ---------------- per-lane constants ----------------
    const int sRow = lane >> 4;            // batch half
    const int sM   = lane & 15;
    const bool sAct = (sM < 9);
    const bool eAct = (sM < 6);

    float bql, bkl, bvl, bcombL, bfL, lngL, lnbL, bbL;
    float exC = 0.f;
    int   eoffG = 0;
    int   qOffS = 0;                       // smem float offset (per parity)
    int   kOffS = 0;                       // intra K/V smem offset
    int   kOffG = 0;                       // halo global offset
    unsigned vTag = 0;                     // intra: offset; halo: 0x80000000|off
    bool  intra = true;

    {
        float c0 = (float)r  * (1.f / 64.f);
        float c1 = (float)cI * (1.f / 64.f);
        int rc  = min(max(r, 1), 62);
        int ccn = min(max(cI, 1), 62);
        int qslot = (rc - tr * 4) * 8 + (ccn - tc * 8);   // always in own tile
        qOffS = (qslot * 2 + sRow) * KPAD;
        if (sAct) {
            int nr = rc + sM / 3 - 1;
            int nc = ccn + sM % 3 - 1;
            intra = (nr >= tr * 4) && (nr < tr * 4 + 4) &&
                    (nc >= tc * 8) && (nc < tc * 8 + 8);
            if (intra) {
                int slot = (nr - tr * 4) * 8 + (nc - tc * 8);
                kOffS = (slot * 2 + sRow) * KPAD;
                vTag  = (unsigned)kOffS;
            } else {
                kOffG = (sRow * PP + nr * 64 + nc) * KPAD;
                vTag  = 0x80000000u | (unsigned)kOffG;
            }
        }

        bql = b_in[lane]      + c0 * W_in[lane * 34 + 32]      + c1 * W_in[lane * 34 + 33];
        bkl = b_in[34 + lane] + c0 * W_in[(34 + lane) * 34 + 32] + c1 * W_in[(34 + lane) * 34 + 33];
        bvl = b_in[68 + lane] + c0 * W_in[(68 + lane) * 34 + 32] + c1 * W_in[(68 + lane) * 34 + 33];
        bcombL = b_x2h[lane] + b_h2h[lane];
        bfL  = b_fc2[lane];
        lngL = ln_g[lane];
        lnbL = ln_b[lane];
        {
            float acc = b_fcsa[lane];
            for (int g = 0; g < 34; g++) acc += b_out[g] * W_fcsa[lane * 34 + g];
            bbL = acc;
        }
        if (eAct) {
            int row = (sM >> 1) * 34 + 32 + (sM & 1);
            exC = b_in[row] + c0 * W_in[row * 34 + 32] + c1 * W_in[row * 34 + 33];
            eoffG = (sRow * PP + p) * KPAD + 32 + (sM & 1);
        }
        // zero h staging + global K/V row pads (elements 34,35) once
        ((float*)sm->RB[wid][0])[36 + lane] = 0.f;
        ((float*)sm->RB[wid][1])[36 + lane] = 0.f;
        if (lane < 2) {
#pragma unroll
            for (int par = 0; par < 2; par++) {
#pragma unroll
                for (int row = 0; row < 2; row++) {
                    size_t o = (size_t)(row * PP + p) * KPAD + 34 + lane;
                    g_K[par][o] = 0.f; g_V[par][o] = 0.f;
                }
            }
        }
    }
    __syncthreads();

    const unsigned base = sm->base;
    const int r0Off = p * KPAD + lane;
    const int r1Off = (PP + p) * KPAD + lane;
    const int sOff0 = (ownSlot * 2 + 0) * KPAD + lane;
    const int sOff1 = (ownSlot * 2 + 1) * KPAD + lane;

    float4* RB0 = sm->RB[wid][0];
    float4* RB1 = sm->RB[wid][1];
    float*  RB0f = (float*)RB0;
    float*  RB1f = (float*)RB1;

    float h0 = 0.f, h1 = 0.f, ht0 = 0.f, ht1 = 0.f;

    for (int t = 0; t < TSTEPS; t++) {
        const int buf = t & 1;
        const int smB = buf * TBUF;
        float* Kb = g_K[buf];
        float* Vb = g_V[buf];

        // =============== PHASE 1: RNN cell + QKV produce ===============
        {
            if (t < NOBS) {
                RB0f[lane] = x[((size_t)t * NROWS + p) * HH + lane];
                RB1f[lane] = x[((size_t)t * NROWS + PP + p) * HH + lane];
            }
            __syncwarp();

            float a0 = bcombL, a1 = bcombL;
#pragma unroll
            for (int c = 0; c < 16; c++) {
                float4 w  = sm->Wc[lane][c];
                int dc = (c < 8) ? c : c + 1;     // h lives at chunks 9..16
                a0 += dot4(RB0[dc], w);
                a1 += dot4(RB1[dc], w);
            }
            ht0 = ftanh(a0);
            ht1 = ftanh(a1);

            __syncwarp();
            RB0f[lane] = ht0;    // stage ht in chunks 0..7
            RB1f[lane] = ht1;
            __syncwarp();

            float q0 = bql, k0 = bkl, v0 = bvl;
            float q1 = bql, k1 = bkl, v1 = bvl;
#pragma unroll
            for (int c = 0; c < 8; c++) {
                float4 wq = sm->Wq[lane][c];
                float4 wk = sm->Wk[lane][c];
                float4 wv = sm->Wv[lane][c];
                float4 t0 = RB0[c];
                float4 t1 = RB1[c];
                q0 += dot4(t0, wq); k0 += dot4(t0, wk); v0 += dot4(t0, wv);
                q1 += dot4(t1, wq); k1 += dot4(t1, wk); v1 += dot4(t1, wv);
            }
            // smem tile copies (parity buf)
            sm->sQ[smB + sOff0] = q0; sm->sK[smB + sOff0] = k0; sm->sV[smB + sOff0] = v0;
            sm->sQ[smB + sOff1] = q1; sm->sK[smB + sOff1] = k1; sm->sV[smB + sOff1] = v1;
            // global copies for halo consumers (K/V only)
            Kb[r0Off] = k0; Vb[r0Off] = v0;
            Kb[r1Off] = k1; Vb[r1Off] = v1;

            // ext elements e=32,33: lanes 0-5 batch0, 16-21 batch1
            if (eAct) {
                const float4* htp = sRow ? RB1 : RB0;
                float ex = exC;
#pragma unroll
                for (int c = 0; c < 8; c++)
                    ex += dot4(htp[c], sm->We[sM][c]);
                int sExt = smB + (ownSlot * 2 + sRow) * KPAD + 32 + (sM & 1);
                if (sM < 2) {
                    sm->sQ[sExt] = ex;
                } else if (sM < 4) {
                    sm->sK[sExt] = ex; Kb[eoffG] = ex;
                } else {
                    sm->sV[sExt] = ex; Vb[eoffG] = ex;
                }
            }
        }

        // ========= LOCAL SYNC: publish own flag, wait 8 tile neighbors =========
        {
            __syncthreads();                       // CTA: all phase-1 stores done
            unsigned want = base + (unsigned)t + 1u;
            if (tid == 0)
                stReleaseGpu(&g_P[bid * 32], want);
            if (tid < 8) {
                while ((int)(ldAcquireGpu(nbF) - want) < 0)
                    __nanosleep(16);
            }
            __syncthreads();                       // broadcast acquire
        }

        // =============== PHASE 2: attention + update + pred ===============
        {
            float sc = -3.4e38f;
            if (sAct) {
                const float4* qrow = (const float4*)(sm->sQ + smB + qOffS);
                const float4* kpS  = (const float4*)(sm->sK + smB + kOffS);
                const float4* kpG  = (const float4*)(Kb + kOffG);
                float d = 0.f;
#pragma unroll
                for (int c = 0; c < 9; c++) {
                    float4 kc = intra ? kpS[c] : __ldcg(kpG + c);
                    d += dot4(qrow[c], kc);
                }
                sc = d;
            }
            // group softmax over 9 within each 16-lane half
            float mx = sc;
#pragma unroll
            for (int o = 8; o > 0; o >>= 1)
                mx = fmaxf(mx, __shfl_xor_sync(0xffffffffu, mx, o, 16));
            float ew = __expf((sc - mx) * INV_SQRT_E);
            float ssum = ew;
#pragma unroll
            for (int o = 8; o > 0; o >>= 1)
                ssum += __shfl_xor_sync(0xffffffffu, ssum, o, 16);
            float wgt = ew * __fdividef(1.f, ssum);

            // V mix: lane c of each half accumulates o-chunk c
            float4 o4 = make_float4(0.f, 0.f, 0.f, 0.f);
#pragma unroll
            for (int m = 0; m < 9; m++) {
                float wm   = __shfl_sync(0xffffffffu, wgt, m, 16);
                unsigned tg = __shfl_sync(0xffffffffu, vTag, m, 16);
                if (sAct) {
                    float4 vv;
                    if ((int)tg < 0)
                        vv = __ldcg((const float4*)(Vb + (tg & 0x7fffffffu)) + sM);
                    else
                        vv = *((const float4*)(sm->sV + smB + tg) + sM);
                    o4.x = fmaf(wm, vv.x, o4.x);
                    o4.y = fmaf(wm, vv.y, o4.y);
                    o4.z = fmaf(wm, vv.z, o4.z);
                    o4.w = fmaf(wm, vv.w, o4.w);
                }
            }
            if (sAct) (sRow ? RB1 : RB0)[sM] = o4;   // o chunks 0..8
            __syncwarp();

            // fused out-proj + fcsa: h = ht + o @ M^T + bb
            float d0 = bbL, d1 = bbL;
#pragma unroll
            for (int c = 0; c < 9; c++) {
                float4 wt = sm->Mw[lane][c];
                d0 += dot4(RB0[c], wt);
                d1 += dot4(RB1[c], wt);
            }
            h0 = ht0 + d0;
            h1 = ht1 + d1;

            RB0f[36 + lane] = h0;   // h chunks 9..16
            RB1f[36 + lane] = h1;
            __syncwarp();

            // fc2 + layernorm -> pred
            float y0 = bfL, y1 = bfL;
#pragma unroll
            for (int c = 0; c < 8; c++) {
                float4 wt = sm->Wf[lane][c];
                y0 += dot4(RB0[9 + c], wt);
                y1 += dot4(RB1[9 + c], wt);
            }
            float m0 = warpAllSum(y0) * (1.f / 32.f);
            float dd0 = y0 - m0;
            float var0 = warpAllSum(dd0 * dd0) * (1.f / 32.f);
            float pred0 = dd0 * rsqrtf(var0 + 1e-5f) * lngL + lnbL;
            float m1 = warpAllSum(y1) * (1.f / 32.f);
            float dd1 = y1 - m1;
            float var1 = warpAllSum(dd1 * dd1) * (1.f / 32.f);
            float pred1 = dd1 * rsqrtf(var1 + 1e-5f) * lngL + lnbL;

            RB0f[lane] = pred0;     // stage as next-step input (chunks 0..7)
            RB1f[lane] = pred1;

            out[((size_t)t * NROWS + p) * HH + lane]      = pred0;
            out[((size_t)t * NROWS + PP + p) * HH + lane] = pred1;
        }
    }
}

extern "C" void kernel_launch(void* const* d_in, const int* in_sizes, int n_in,
                              void* d_out, int out_size) {
    (void)in_sizes; (void)n_in; (void)out_size;
    cudaFuncSetAttribute(rnn_kernel, cudaFuncAttributeMaxDynamicSharedMemorySize,
                         (int)sizeof(Smem));
    rnn_kernel<<<NBLK, NTHR, sizeof(Smem)>>>(
        (const float*)d_in[0],
        (const float*)d_in[1],  (const float*)d_in[2],
        (const float*)d_in[3],  (const float*)d_in[4],
        (const float*)d_in[5],  (const float*)d_in[6],
        (const float*)d_in[7],  (const float*)d_in[8],
        (const float*)d_in[9],  (const float*)d_in[10],
        (const float*)d_in[11], (const float*)d_in[12],
        (const float*)d_in[13], (const float*)d_in[14],
        (float*)d_out);
}